// round 4
// baseline (speedup 1.0000x reference)
#include <cuda_runtime.h>
#include <cuda_bf16.h>
#include <cstdint>
#include <math.h>

#define BB 4
#define SS 2048
#define DD 1024
#define EE 1536
#define HH 4096
#define TT (BB*SS)   /* 8192 tokens */

typedef __nv_bfloat16 bf16;

// ---------------- scratch (allocation-free: __device__ globals) ----------------
__device__ bf16  g_dwh[(size_t)TT*DD], g_dwl[(size_t)TT*DD];
__device__ float g_t1 [(size_t)TT*DD];
__device__ bf16  g_x1h[(size_t)TT*DD], g_x1l[(size_t)TT*DD];
__device__ float g_gates[(size_t)3*TT*EE];     // [lgf | lgi | lgth] planes
__device__ bf16  g_hh [(size_t)TT*EE], g_hl [(size_t)TT*EE];
__device__ bf16  g_x2h[(size_t)TT*DD], g_x2l[(size_t)TT*DD];
__device__ bf16  g_mh [(size_t)TT*HH], g_ml [(size_t)TT*HH];
// weight hi/lo
__device__ bf16 g_pwh[DD*DD], g_pwl[DD*DD];
__device__ bf16 g_wgh[3*EE*DD], g_wgl[3*EE*DD];   // concat [w_f; w_i; w_h]
__device__ bf16 g_wdh[DD*EE], g_wdl[DD*EE];
__device__ bf16 g_m1h[HH*DD], g_m1l[HH*DD];
__device__ bf16 g_m2h[DD*HH], g_m2l[DD*HH];

// ---------------- math helpers ----------------
__device__ __forceinline__ float logsig(float z) {
    return z >= 0.f ? -log1pf(expf(-z)) : z - log1pf(expf(z));
}
__device__ __forceinline__ float loggf(float x) {
    return x >= 0.f ? logf(x + 0.5f) : logsig(x);
}
__device__ __forceinline__ float gelu_exact(float x) {
    return 0.5f * x * (1.f + erff(x * 0.70710678118654752f));
}
template<int ACT>
__device__ __forceinline__ float apply_act(float v) {
    if (ACT == 1) return logsig(v);
    if (ACT == 2) return loggf(v);
    if (ACT == 3) return gelu_exact(v);
    return v;
}

__device__ __forceinline__ uint32_t smem_u32(const void* p) {
    uint32_t a;
    asm("{ .reg .u64 t; cvta.to.shared.u64 t, %1; cvt.u32.u64 %0, t; }" : "=r"(a) : "l"(p));
    return a;
}

#define LDMX4(d0,d1,d2,d3,addr) \
    asm volatile("ldmatrix.sync.aligned.m8n8.x4.shared.b16 {%0,%1,%2,%3}, [%4];" \
        : "=r"(d0), "=r"(d1), "=r"(d2), "=r"(d3) : "r"(addr))

__device__ __forceinline__ void mma16816(float* c, const uint32_t* a, const uint32_t* b) {
    asm volatile(
        "mma.sync.aligned.m16n8k16.row.col.f32.bf16.bf16.f32 "
        "{%0,%1,%2,%3}, {%4,%5,%6,%7}, {%8,%9}, {%0,%1,%2,%3};"
        : "+f"(c[0]), "+f"(c[1]), "+f"(c[2]), "+f"(c[3])
        : "r"(a[0]), "r"(a[1]), "r"(a[2]), "r"(a[3]), "r"(b[0]), "r"(b[1]));
}

// ---------------- HMMA GEMM: C[M,N] = (Ah+Al)[M,K] @ (Bh+Bl)[N,K]^T ----------------
// 128x128 tile, BK=64, 8 warps (2x4), bf16x3, 3-stage cp.async pipeline.
// ACT==4: fused gate mode (N=3*EE concat; per-region act; writes fp32 planes).
static const int TILE_B  = 16384;              // 128 rows x 128B (swizzled)
static const int STAGE_B = 4 * TILE_B;         // Ah, Al, Bh, Bl
static const int GEMM_SMEM = 3 * STAGE_B + 1024;

template<int ACT, bool OUTF, bool OUTB>
__global__ __launch_bounds__(256, 1)
void hm_gemm(const bf16* __restrict__ Ah, const bf16* __restrict__ Al,
             const bf16* __restrict__ Bh, const bf16* __restrict__ Bl,
             const float* __restrict__ bias, const float* __restrict__ res,
             float* __restrict__ Cf, bf16* __restrict__ Ch, bf16* __restrict__ Cl,
             int M, int N, int K)
{
    extern __shared__ char smem[];
    uint32_t sb = (smem_u32(smem) + 1023) & ~1023u;
    int tid = threadIdx.x;
    int lane = tid & 31, wid = tid >> 5;
    int wm = wid & 1, wn = wid >> 1;          // 2 x 4 warp grid
    int bm = blockIdx.y * 128, bn = blockIdx.x * 128;
    const int NK = K >> 6;

    float acc[4][4][4];
    #pragma unroll
    for (int i = 0; i < 4; i++)
        #pragma unroll
        for (int j = 0; j < 4; j++)
            #pragma unroll
            for (int q = 0; q < 4; q++) acc[i][j][q] = 0.f;

    auto load_chunk = [&](int c) {
        uint32_t tb = sb + (c % 3) * STAGE_B;
        int k0 = c << 6;
        #pragma unroll
        for (int i = 0; i < 16; i++) {
            int idx = tid + (i << 8);
            int t = i >> 2;                   // tile 0..3 (const per i)
            int r = (idx >> 3) & 127;
            int ch = idx & 7;
            const bf16* base = (t == 0) ? Ah : (t == 1) ? Al : (t == 2) ? Bh : Bl;
            int rowoff = (t < 2) ? bm : bn;
            const bf16* src = base + (size_t)(rowoff + r) * K + k0 + ch * 8;
            uint32_t dst = tb + t * TILE_B + r * 128 + ((ch ^ (r & 7)) * 16);
            asm volatile("cp.async.cg.shared.global [%0], [%1], 16;" :: "r"(dst), "l"(src));
        }
        asm volatile("cp.async.commit_group;");
    };

    load_chunk(0);
    load_chunk(1);

    for (int c = 0; c < NK; c++) {
        if (c + 2 < NK) {
            load_chunk(c + 2);
            asm volatile("cp.async.wait_group 2;");
        } else if (c + 1 < NK) {
            asm volatile("cp.async.wait_group 1;");
        } else {
            asm volatile("cp.async.wait_group 0;");
        }
        __syncthreads();

        uint32_t tb  = sb + (c % 3) * STAGE_B;
        uint32_t tAh = tb;
        uint32_t tAl = tb + TILE_B;
        uint32_t tBh = tb + 2 * TILE_B;
        uint32_t tBl = tb + 3 * TILE_B;

        int khalf = lane >> 4;
        int rlo = lane & 15;

        #pragma unroll
        for (int sub = 0; sub < 4; sub++) {      // k16 sub-steps within BK=64
            int c16 = sub * 2 + khalf;
            uint32_t ahf[4][4], alf[4][4], bh[4][2], bl[4][2];
            #pragma unroll
            for (int p = 0; p < 2; p++) {
                int r = wn * 32 + p * 16 + rlo;
                uint32_t addr = r * 128 + ((c16 ^ (r & 7)) * 16);
                uint32_t t0, t1, t2, t3;
                LDMX4(t0, t1, t2, t3, tBh + addr);
                bh[2*p][0] = t0; bh[2*p][1] = t2; bh[2*p+1][0] = t1; bh[2*p+1][1] = t3;
                uint32_t u0, u1, u2, u3;
                LDMX4(u0, u1, u2, u3, tBl + addr);
                bl[2*p][0] = u0; bl[2*p][1] = u2; bl[2*p+1][0] = u1; bl[2*p+1][1] = u3;
            }
            #pragma unroll
            for (int i = 0; i < 4; i++) {
                int r = wm * 64 + i * 16 + rlo;
                uint32_t addr = r * 128 + ((c16 ^ (r & 7)) * 16);
                LDMX4(ahf[i][0], ahf[i][1], ahf[i][2], ahf[i][3], tAh + addr);
                LDMX4(alf[i][0], alf[i][1], alf[i][2], alf[i][3], tAl + addr);
            }
            // pass 1: Ah*Bh — 16 independent accumulators
            #pragma unroll
            for (int i = 0; i < 4; i++)
                #pragma unroll
                for (int j = 0; j < 4; j++) mma16816(acc[i][j], ahf[i], bh[j]);
            // pass 2: Ah*Bl
            #pragma unroll
            for (int i = 0; i < 4; i++)
                #pragma unroll
                for (int j = 0; j < 4; j++) mma16816(acc[i][j], ahf[i], bl[j]);
            // pass 3: Al*Bh
            #pragma unroll
            for (int i = 0; i < 4; i++)
                #pragma unroll
                for (int j = 0; j < 4; j++) mma16816(acc[i][j], alf[i], bh[j]);
        }
        __syncthreads();
    }

    // ---- epilogue ----
    int gate = 0;
    float* gout = Cf;
    int cshift = 0;
    int Nout = N;
    if (ACT == 4) {
        gate = bn / EE;                         // 0:f 1:i 2:th
        gout = Cf + (size_t)gate * ((size_t)TT * EE);
        cshift = gate * EE;
        Nout = EE;
    }
    #pragma unroll
    for (int i = 0; i < 4; i++) {
        #pragma unroll
        for (int j = 0; j < 4; j++) {
            int r0 = bm + wm * 64 + i * 16 + (lane >> 2);
            int c0g = bn + wn * 32 + j * 8 + (lane & 3) * 2;    // global col
            int c0 = c0g - cshift;                               // output col
            #pragma unroll
            for (int half = 0; half < 2; half++) {
                int row = r0 + half * 8;
                float v0 = acc[i][j][half * 2 + 0];
                float v1 = acc[i][j][half * 2 + 1];
                if (bias) { v0 += __ldg(bias + c0g); v1 += __ldg(bias + c0g + 1); }
                if (ACT == 4) {
                    if (gate < 2) { v0 = logsig(v0); v1 = logsig(v1); }
                    else          { v0 = loggf(v0);  v1 = loggf(v1); }
                } else {
                    v0 = apply_act<ACT>(v0);
                    v1 = apply_act<ACT>(v1);
                }
                size_t o = (size_t)row * Nout + c0;
                if (res) {
                    float2 r2 = *(const float2*)(res + o);
                    v0 += r2.x; v1 += r2.y;
                }
                if (OUTF || ACT == 4) {
                    float2 w2; w2.x = v0; w2.y = v1;
                    *(float2*)(gout + o) = w2;
                }
                if (OUTB) {
                    bf16 h0 = __float2bfloat16(v0);
                    bf16 h1 = __float2bfloat16(v1);
                    __nv_bfloat162 h2; h2.x = h0; h2.y = h1;
                    __nv_bfloat162 l2;
                    l2.x = __float2bfloat16(v0 - __bfloat162float(h0));
                    l2.y = __float2bfloat16(v1 - __bfloat162float(h1));
                    *(__nv_bfloat162*)(Ch + o) = h2;
                    *(__nv_bfloat162*)(Cl + o) = l2;
                }
            }
        }
    }
}

// ---------------- weight split fp32 -> hi/lo bf16 ----------------
__global__ void split_kernel(const float* __restrict__ w, bf16* __restrict__ hi,
                             bf16* __restrict__ lo, int n4) {
    int i = blockIdx.x * blockDim.x + threadIdx.x;
    if (i >= n4) return;
    float4 x = ((const float4*)w)[i];
    __nv_bfloat162 h0, h1, l0, l1;
    h0.x = __float2bfloat16(x.x); h0.y = __float2bfloat16(x.y);
    h1.x = __float2bfloat16(x.z); h1.y = __float2bfloat16(x.w);
    l0.x = __float2bfloat16(x.x - __bfloat162float(h0.x));
    l0.y = __float2bfloat16(x.y - __bfloat162float(h0.y));
    l1.x = __float2bfloat16(x.z - __bfloat162float(h1.x));
    l1.y = __float2bfloat16(x.w - __bfloat162float(h1.y));
    ((__nv_bfloat162*)hi)[2*i]   = h0;
    ((__nv_bfloat162*)hi)[2*i+1] = h1;
    ((__nv_bfloat162*)lo)[2*i]   = l0;
    ((__nv_bfloat162*)lo)[2*i+1] = l1;
}

// ---------------- depthwise causal conv (K=4), emits hi/lo bf16 ----------------
__global__ void dwconv_kernel(const float* __restrict__ x,
                              const float* __restrict__ w,
                              const float* __restrict__ b,
                              bf16* __restrict__ oh, bf16* __restrict__ ol) {
    int idx = blockIdx.x * blockDim.x + threadIdx.x;
    int d = idx & (DD - 1);
    int t = idx >> 10;
    int s = t & (SS - 1);
    float acc = b[d];
    float w0 = w[d*4+0], w1 = w[d*4+1], w2 = w[d*4+2], w3 = w[d*4+3];
    if (s >= 3) acc += w0 * x[(size_t)(t-3)*DD + d];
    if (s >= 2) acc += w1 * x[(size_t)(t-2)*DD + d];
    if (s >= 1) acc += w2 * x[(size_t)(t-1)*DD + d];
    acc += w3 * x[(size_t)t*DD + d];
    bf16 h = __float2bfloat16(acc);
    oh[idx] = h;
    ol[idx] = __float2bfloat16(acc - __bfloat162float(h));
}

// ---------------- LayerNorm (D=1024), emits hi/lo bf16 ----------------
__global__ void ln_kernel(const float* __restrict__ in, const float* __restrict__ g,
                          const float* __restrict__ beta,
                          bf16* __restrict__ oh, bf16* __restrict__ ol) {
    int t = blockIdx.x;
    int i = threadIdx.x;   // 0..255, each a float4
    float4 v = ((const float4*)(in + (size_t)t*DD))[i];
    float s  = v.x + v.y + v.z + v.w;
    float s2 = v.x*v.x + v.y*v.y + v.z*v.z + v.w*v.w;
    #pragma unroll
    for (int o = 16; o; o >>= 1) {
        s  += __shfl_xor_sync(0xffffffffu, s,  o);
        s2 += __shfl_xor_sync(0xffffffffu, s2, o);
    }
    __shared__ float ss[8], ss2[8];
    int w = i >> 5, l = i & 31;
    if (!l) { ss[w] = s; ss2[w] = s2; }
    __syncthreads();
    if (w == 0) {
        s  = (l < 8) ? ss[l]  : 0.f;
        s2 = (l < 8) ? ss2[l] : 0.f;
        #pragma unroll
        for (int o = 4; o; o >>= 1) {
            s  += __shfl_xor_sync(0xffffffffu, s,  o);
            s2 += __shfl_xor_sync(0xffffffffu, s2, o);
        }
        if (!l) { ss[0] = s; ss2[0] = s2; }
    }
    __syncthreads();
    float mu  = ss[0] * (1.f / DD);
    float var = ss2[0] * (1.f / DD) - mu * mu;
    float inv = rsqrtf(var + 1e-5f);
    float4 gg = ((const float4*)g)[i];
    float4 bb = ((const float4*)beta)[i];
    float o0 = (v.x - mu) * inv * gg.x + bb.x;
    float o1 = (v.y - mu) * inv * gg.y + bb.y;
    float o2 = (v.z - mu) * inv * gg.z + bb.z;
    float o3 = (v.w - mu) * inv * gg.w + bb.w;
    __nv_bfloat162 h0, h1, l0, l1;
    h0.x = __float2bfloat16(o0); h0.y = __float2bfloat16(o1);
    h1.x = __float2bfloat16(o2); h1.y = __float2bfloat16(o3);
    l0.x = __float2bfloat16(o0 - __bfloat162float(h0.x));
    l0.y = __float2bfloat16(o1 - __bfloat162float(h0.y));
    l1.x = __float2bfloat16(o2 - __bfloat162float(h1.x));
    l1.y = __float2bfloat16(o3 - __bfloat162float(h1.y));
    size_t base = (size_t)t * DD;
    ((__nv_bfloat162*)(oh + base))[2*i]   = h0;
    ((__nv_bfloat162*)(oh + base))[2*i+1] = h1;
    ((__nv_bfloat162*)(ol + base))[2*i]   = l0;
    ((__nv_bfloat162*)(ol + base))[2*i+1] = l1;
}

// ---------------- minLSTM log-space scan, emits h as hi/lo bf16 ----------------
__global__ void scan_kernel(const float* __restrict__ gates,
                            bf16* __restrict__ hh, bf16* __restrict__ hl) {
    int id = blockIdx.x * blockDim.x + threadIdx.x;
    if (id >= BB * EE) return;
    int b = id / EE, e = id % EE;
    const float* lf  = gates + (size_t)b * SS * EE + e;
    const float* lgi = lf + (size_t)TT * EE;
    const float* lth = lf + (size_t)2 * TT * EE;
    bf16* ph = hh + (size_t)b * SS * EE + e;
    bf16* pl = hl + (size_t)b * SS * EE + e;
    float A = 0.f;
    float m = -0.6931471805599453f;   // log(0.5) - 0
    float r = 1.f;
    #pragma unroll 4
    for (int s = 0; s < SS; s++) {
        size_t off = (size_t)s * EE;
        A += lf[off];
        float t = lgi[off] + lth[off] - A;
        if (t <= m) {
            r += expf(t - m);
        } else {
            r = r * expf(m - t) + 1.f;
            m = t;
        }
        float h = expf(A + m) * r;
        bf16 hb = __float2bfloat16(h);
        ph[off] = hb;
        pl[off] = __float2bfloat16(h - __bfloat162float(hb));
    }
}

// ---------------- launch ----------------
extern "C" void kernel_launch(void* const* d_in, const int* in_sizes, int n_in,
                              void* d_out, int out_size) {
    const float* x      = (const float*)d_in[0];
    const float* cdw_w  = (const float*)d_in[1];
    const float* cdw_b  = (const float*)d_in[2];
    const float* cpw_w  = (const float*)d_in[3];
    const float* cpw_b  = (const float*)d_in[4];
    const float* ln1_g  = (const float*)d_in[5];
    const float* ln1_b  = (const float*)d_in[6];
    const float* w_f    = (const float*)d_in[7];
    const float* w_i    = (const float*)d_in[8];
    const float* w_h    = (const float*)d_in[9];
    const float* w_down = (const float*)d_in[10];
    const float* ln2_g  = (const float*)d_in[11];
    const float* ln2_b  = (const float*)d_in[12];
    const float* mlp_w1 = (const float*)d_in[13];
    const float* mlp_b1 = (const float*)d_in[14];
    const float* mlp_w2 = (const float*)d_in[15];
    const float* mlp_b2 = (const float*)d_in[16];
    float* out = (float*)d_out;

    bf16 *dwh, *dwl, *x1h, *x1l, *hhp, *hlp, *x2h, *x2l, *mh, *ml;
    bf16 *pwh, *pwl, *wgh, *wgl, *wdh, *wdl, *m1h, *m1l, *m2h, *m2l;
    float *t1, *gates;
    cudaGetSymbolAddress((void**)&dwh, g_dwh); cudaGetSymbolAddress((void**)&dwl, g_dwl);
    cudaGetSymbolAddress((void**)&t1,  g_t1);
    cudaGetSymbolAddress((void**)&x1h, g_x1h); cudaGetSymbolAddress((void**)&x1l, g_x1l);
    cudaGetSymbolAddress((void**)&gates, g_gates);
    cudaGetSymbolAddress((void**)&hhp, g_hh);  cudaGetSymbolAddress((void**)&hlp, g_hl);
    cudaGetSymbolAddress((void**)&x2h, g_x2h); cudaGetSymbolAddress((void**)&x2l, g_x2l);
    cudaGetSymbolAddress((void**)&mh,  g_mh);  cudaGetSymbolAddress((void**)&ml,  g_ml);
    cudaGetSymbolAddress((void**)&pwh, g_pwh); cudaGetSymbolAddress((void**)&pwl, g_pwl);
    cudaGetSymbolAddress((void**)&wgh, g_wgh); cudaGetSymbolAddress((void**)&wgl, g_wgl);
    cudaGetSymbolAddress((void**)&wdh, g_wdh); cudaGetSymbolAddress((void**)&wdl, g_wdl);
    cudaGetSymbolAddress((void**)&m1h, g_m1h); cudaGetSymbolAddress((void**)&m1l, g_m1l);
    cudaGetSymbolAddress((void**)&m2h, g_m2h); cudaGetSymbolAddress((void**)&m2l, g_m2l);

    cudaFuncSetAttribute(hm_gemm<0,true,false>, cudaFuncAttributeMaxDynamicSharedMemorySize, GEMM_SMEM);
    cudaFuncSetAttribute(hm_gemm<4,true,false>, cudaFuncAttributeMaxDynamicSharedMemorySize, GEMM_SMEM);
    cudaFuncSetAttribute(hm_gemm<3,false,true>, cudaFuncAttributeMaxDynamicSharedMemorySize, GEMM_SMEM);

    // weight splits (w_f/w_i/w_h concatenated into one [3E, D] buffer)
    split_kernel<<<(DD*DD/4 + 255)/256, 256>>>(cpw_w,  pwh, pwl, DD*DD/4);
    split_kernel<<<(EE*DD/4 + 255)/256, 256>>>(w_f, wgh,             wgl,             EE*DD/4);
    split_kernel<<<(EE*DD/4 + 255)/256, 256>>>(w_i, wgh + (size_t)EE*DD,   wgl + (size_t)EE*DD,   EE*DD/4);
    split_kernel<<<(EE*DD/4 + 255)/256, 256>>>(w_h, wgh + (size_t)2*EE*DD, wgl + (size_t)2*EE*DD, EE*DD/4);
    split_kernel<<<(DD*EE/4 + 255)/256, 256>>>(w_down, wdh, wdl, DD*EE/4);
    split_kernel<<<(HH*DD/4 + 255)/256, 256>>>(mlp_w1, m1h, m1l, HH*DD/4);
    split_kernel<<<(DD*HH/4 + 255)/256, 256>>>(mlp_w2, m2h, m2l, DD*HH/4);

    // 1) depthwise causal conv -> dw hi/lo
    dwconv_kernel<<<(TT*DD)/256, 256>>>(x, cdw_w, cdw_b, dwh, dwl);

    // 2) pointwise conv + bias + residual(x) -> t1 (fp32)
    hm_gemm<0,true,false><<<dim3(DD/128, TT/128), 256, GEMM_SMEM>>>(
        dwh, dwl, pwh, pwl, cpw_b, x, t1, nullptr, nullptr, TT, DD, DD);

    // 3) LN1 -> x1 hi/lo
    ln_kernel<<<TT, 256>>>(t1, ln1_g, ln1_b, x1h, x1l);

    // 4) fused gate GEMM (f|i|h), per-region activation -> gates planes
    hm_gemm<4,true,false><<<dim3(3*EE/128, TT/128), 256, GEMM_SMEM>>>(
        x1h, x1l, wgh, wgl, nullptr, nullptr, gates, nullptr, nullptr, TT, 3*EE, DD);

    // 5) scan -> h hi/lo
    scan_kernel<<<(BB*EE + 127)/128, 128>>>(gates, hhp, hlp);

    // 6) down GEMM + residual(x) -> t1
    hm_gemm<0,true,false><<<dim3(DD/128, TT/128), 256, GEMM_SMEM>>>(
        hhp, hlp, wdh, wdl, nullptr, x, t1, nullptr, nullptr, TT, DD, EE);

    // 7) LN2 -> x2 hi/lo
    ln_kernel<<<TT, 256>>>(t1, ln2_g, ln2_b, x2h, x2l);

    // 8) MLP up + bias + GELU -> hmid hi/lo
    hm_gemm<3,false,true><<<dim3(HH/128, TT/128), 256, GEMM_SMEM>>>(
        x2h, x2l, m1h, m1l, mlp_b1, nullptr, nullptr, mh, ml, TT, HH, DD);

    // 9) MLP down + bias -> out (fp32)
    hm_gemm<0,true,false><<<dim3(DD/128, TT/128), 256, GEMM_SMEM>>>(
        mh, ml, m2h, m2l, mlp_b2, nullptr, out, nullptr, nullptr, TT, DD, HH);
}

// round 5
// speedup vs baseline: 1.6141x; 1.6141x over previous
#include <cuda_runtime.h>
#include <cuda_fp16.h>
#include <cstdint>
#include <math.h>

#define BB 4
#define SS 2048
#define DD 1024
#define EE 1536
#define HH 4096
#define TT (BB*SS)   /* 8192 tokens */

typedef __half fp16;

// ---------------- scratch (allocation-free: __device__ globals) ----------------
__device__ fp16  g_dwa[(size_t)TT*DD];         // dwconv out (A of pw gemm)
__device__ float g_t1 [(size_t)TT*DD];
__device__ fp16  g_x1a[(size_t)TT*DD];         // post-LN1
__device__ float g_gates[(size_t)3*TT*EE];     // [lgf | lgi | lgth] planes
__device__ fp16  g_ha [(size_t)TT*EE];         // scan output h
__device__ fp16  g_x2a[(size_t)TT*DD];         // post-LN2
__device__ fp16  g_ma [(size_t)TT*HH];         // MLP mid
// weight hi/lo (fp16 split)
__device__ fp16 g_pwh[DD*DD], g_pwl[DD*DD];
__device__ fp16 g_wgh[3*EE*DD], g_wgl[3*EE*DD];   // concat [w_f; w_i; w_h]
__device__ fp16 g_wdh[DD*EE], g_wdl[DD*EE];
__device__ fp16 g_m1h[HH*DD], g_m1l[HH*DD];
__device__ fp16 g_m2h[DD*HH], g_m2l[DD*HH];

// ---------------- math helpers ----------------
__device__ __forceinline__ float logsig(float z) {
    return z >= 0.f ? -log1pf(expf(-z)) : z - log1pf(expf(z));
}
__device__ __forceinline__ float loggf(float x) {
    return x >= 0.f ? logf(x + 0.5f) : logsig(x);
}
__device__ __forceinline__ float gelu_exact(float x) {
    return 0.5f * x * (1.f + erff(x * 0.70710678118654752f));
}
template<int ACT>
__device__ __forceinline__ float apply_act(float v) {
    if (ACT == 1) return logsig(v);
    if (ACT == 2) return loggf(v);
    if (ACT == 3) return gelu_exact(v);
    return v;
}

__device__ __forceinline__ uint32_t smem_u32(const void* p) {
    uint32_t a;
    asm("{ .reg .u64 t; cvta.to.shared.u64 t, %1; cvt.u32.u64 %0, t; }" : "=r"(a) : "l"(p));
    return a;
}

#define LDMX4(d0,d1,d2,d3,addr) \
    asm volatile("ldmatrix.sync.aligned.m8n8.x4.shared.b16 {%0,%1,%2,%3}, [%4];" \
        : "=r"(d0), "=r"(d1), "=r"(d2), "=r"(d3) : "r"(addr))

__device__ __forceinline__ void mma16816(float* c, const uint32_t* a, const uint32_t* b) {
    asm volatile(
        "mma.sync.aligned.m16n8k16.row.col.f32.f16.f16.f32 "
        "{%0,%1,%2,%3}, {%4,%5,%6,%7}, {%8,%9}, {%0,%1,%2,%3};"
        : "+f"(c[0]), "+f"(c[1]), "+f"(c[2]), "+f"(c[3])
        : "r"(a[0]), "r"(a[1]), "r"(a[2]), "r"(a[3]), "r"(b[0]), "r"(b[1]));
}

// ---------------- HMMA GEMM: C[M,N] = A[M,K] @ (Bh+Bl)[N,K]^T ----------------
// A rounded to fp16 once; weights split hi/lo. 2 MMAs per accumulator per k16.
// 128x128 tile, BK=64, 8 warps (2x4), 2-stage cp.async pipeline, 2 CTAs/SM.
static const int TILE_B  = 16384;              // 128 rows x 128B (swizzled)
static const int STAGE_B = 3 * TILE_B;         // A, Bh, Bl
static const int GEMM_SMEM = 2 * STAGE_B + 1024;

template<int ACT, bool OUTF, bool OUTB>
__global__ __launch_bounds__(256, 2)
void hm_gemm(const fp16* __restrict__ A,
             const fp16* __restrict__ Bh, const fp16* __restrict__ Bl,
             const float* __restrict__ bias, const float* __restrict__ res,
             float* __restrict__ Cf, fp16* __restrict__ Ch,
             int M, int N, int K)
{
    extern __shared__ char smem[];
    uint32_t sb = (smem_u32(smem) + 1023) & ~1023u;
    int tid = threadIdx.x;
    int lane = tid & 31, wid = tid >> 5;
    int wm = wid & 1, wn = wid >> 1;          // 2 x 4 warp grid
    int bm = blockIdx.y * 128, bn = blockIdx.x * 128;
    const int NK = K >> 6;

    float acc[4][4][4];
    #pragma unroll
    for (int i = 0; i < 4; i++)
        #pragma unroll
        for (int j = 0; j < 4; j++)
            #pragma unroll
            for (int q = 0; q < 4; q++) acc[i][j][q] = 0.f;

    auto load_chunk = [&](int c) {
        uint32_t tb = sb + (c & 1) * STAGE_B;
        int k0 = c << 6;
        #pragma unroll
        for (int i = 0; i < 12; i++) {
            int idx = tid + (i << 8);
            int t = i >> 2;                   // tile 0..2 (const per i)
            int r = (idx >> 3) & 127;
            int ch = idx & 7;
            const fp16* base = (t == 0) ? A : (t == 1) ? Bh : Bl;
            int rowoff = (t == 0) ? bm : bn;
            const fp16* src = base + (size_t)(rowoff + r) * K + k0 + ch * 8;
            uint32_t dst = tb + t * TILE_B + r * 128 + ((ch ^ (r & 7)) * 16);
            asm volatile("cp.async.cg.shared.global [%0], [%1], 16;" :: "r"(dst), "l"(src));
        }
        asm volatile("cp.async.commit_group;");
    };

    load_chunk(0);

    for (int c = 0; c < NK; c++) {
        if (c + 1 < NK) {
            load_chunk(c + 1);
            asm volatile("cp.async.wait_group 1;");
        } else {
            asm volatile("cp.async.wait_group 0;");
        }
        __syncthreads();

        uint32_t tb  = sb + (c & 1) * STAGE_B;
        uint32_t tA  = tb;
        uint32_t tBh = tb + TILE_B;
        uint32_t tBl = tb + 2 * TILE_B;

        int khalf = lane >> 4;
        int rlo = lane & 15;

        #pragma unroll
        for (int sub = 0; sub < 4; sub++) {      // k16 sub-steps within BK=64
            int c16 = sub * 2 + khalf;
            uint32_t bh[4][2], bl[4][2];
            #pragma unroll
            for (int p = 0; p < 2; p++) {
                int r = wn * 32 + p * 16 + rlo;
                uint32_t addr = r * 128 + ((c16 ^ (r & 7)) * 16);
                uint32_t t0, t1, t2, t3;
                LDMX4(t0, t1, t2, t3, tBh + addr);
                bh[2*p][0] = t0; bh[2*p][1] = t2; bh[2*p+1][0] = t1; bh[2*p+1][1] = t3;
                uint32_t u0, u1, u2, u3;
                LDMX4(u0, u1, u2, u3, tBl + addr);
                bl[2*p][0] = u0; bl[2*p][1] = u2; bl[2*p+1][0] = u1; bl[2*p+1][1] = u3;
            }
            #pragma unroll
            for (int i = 0; i < 4; i++) {
                int r = wm * 64 + i * 16 + rlo;
                uint32_t addr = r * 128 + ((c16 ^ (r & 7)) * 16);
                uint32_t ah[4];
                LDMX4(ah[0], ah[1], ah[2], ah[3], tA + addr);
                #pragma unroll
                for (int j = 0; j < 4; j++) {
                    mma16816(acc[i][j], ah, bh[j]);
                    mma16816(acc[i][j], ah, bl[j]);
                }
            }
        }
        __syncthreads();
    }

    // ---- epilogue ----
    int gate = 0;
    float* gout = Cf;
    int cshift = 0;
    int Nout = N;
    if (ACT == 4) {
        gate = bn / EE;                         // 0:f 1:i 2:th
        gout = Cf + (size_t)gate * ((size_t)TT * EE);
        cshift = gate * EE;
        Nout = EE;
    }
    #pragma unroll
    for (int i = 0; i < 4; i++) {
        #pragma unroll
        for (int j = 0; j < 4; j++) {
            int r0 = bm + wm * 64 + i * 16 + (lane >> 2);
            int c0g = bn + wn * 32 + j * 8 + (lane & 3) * 2;    // global col
            int c0 = c0g - cshift;                               // output col
            #pragma unroll
            for (int half = 0; half < 2; half++) {
                int row = r0 + half * 8;
                float v0 = acc[i][j][half * 2 + 0];
                float v1 = acc[i][j][half * 2 + 1];
                if (bias) { v0 += __ldg(bias + c0g); v1 += __ldg(bias + c0g + 1); }
                if (ACT == 4) {
                    if (gate < 2) { v0 = logsig(v0); v1 = logsig(v1); }
                    else          { v0 = loggf(v0);  v1 = loggf(v1); }
                } else {
                    v0 = apply_act<ACT>(v0);
                    v1 = apply_act<ACT>(v1);
                }
                size_t o = (size_t)row * Nout + c0;
                if (res) {
                    float2 r2 = *(const float2*)(res + o);
                    v0 += r2.x; v1 += r2.y;
                }
                if (OUTF || ACT == 4) {
                    float2 w2; w2.x = v0; w2.y = v1;
                    *(float2*)(gout + o) = w2;
                }
                if (OUTB) {
                    __half2 h2;
                    h2.x = __float2half_rn(v0);
                    h2.y = __float2half_rn(v1);
                    *(__half2*)(Ch + o) = h2;
                }
            }
        }
    }
}

// ---------------- weight split fp32 -> hi/lo fp16 ----------------
__global__ void split_kernel(const float* __restrict__ w, fp16* __restrict__ hi,
                             fp16* __restrict__ lo, int n4) {
    int i = blockIdx.x * blockDim.x + threadIdx.x;
    if (i >= n4) return;
    float4 x = ((const float4*)w)[i];
    __half2 h0, h1, l0, l1;
    h0.x = __float2half_rn(x.x); h0.y = __float2half_rn(x.y);
    h1.x = __float2half_rn(x.z); h1.y = __float2half_rn(x.w);
    l0.x = __float2half_rn(x.x - __half2float(h0.x));
    l0.y = __float2half_rn(x.y - __half2float(h0.y));
    l1.x = __float2half_rn(x.z - __half2float(h1.x));
    l1.y = __float2half_rn(x.w - __half2float(h1.y));
    ((__half2*)hi)[2*i]   = h0;
    ((__half2*)hi)[2*i+1] = h1;
    ((__half2*)lo)[2*i]   = l0;
    ((__half2*)lo)[2*i+1] = l1;
}

// ---------------- depthwise causal conv (K=4), emits fp16 ----------------
__global__ void dwconv_kernel(const float* __restrict__ x,
                              const float* __restrict__ w,
                              const float* __restrict__ b,
                              fp16* __restrict__ oa) {
    int idx = blockIdx.x * blockDim.x + threadIdx.x;
    int d = idx & (DD - 1);
    int t = idx >> 10;
    int s = t & (SS - 1);
    float acc = b[d];
    float w0 = w[d*4+0], w1 = w[d*4+1], w2 = w[d*4+2], w3 = w[d*4+3];
    if (s >= 3) acc += w0 * x[(size_t)(t-3)*DD + d];
    if (s >= 2) acc += w1 * x[(size_t)(t-2)*DD + d];
    if (s >= 1) acc += w2 * x[(size_t)(t-1)*DD + d];
    acc += w3 * x[(size_t)t*DD + d];
    oa[idx] = __float2half_rn(acc);
}

// ---------------- LayerNorm (D=1024), emits fp16 ----------------
__global__ void ln_kernel(const float* __restrict__ in, const float* __restrict__ g,
                          const float* __restrict__ beta, fp16* __restrict__ oa) {
    int t = blockIdx.x;
    int i = threadIdx.x;   // 0..255, each a float4
    float4 v = ((const float4*)(in + (size_t)t*DD))[i];
    float s  = v.x + v.y + v.z + v.w;
    float s2 = v.x*v.x + v.y*v.y + v.z*v.z + v.w*v.w;
    #pragma unroll
    for (int o = 16; o; o >>= 1) {
        s  += __shfl_xor_sync(0xffffffffu, s,  o);
        s2 += __shfl_xor_sync(0xffffffffu, s2, o);
    }
    __shared__ float ss[8], ss2[8];
    int w = i >> 5, l = i & 31;
    if (!l) { ss[w] = s; ss2[w] = s2; }
    __syncthreads();
    if (w == 0) {
        s  = (l < 8) ? ss[l]  : 0.f;
        s2 = (l < 8) ? ss2[l] : 0.f;
        #pragma unroll
        for (int o = 4; o; o >>= 1) {
            s  += __shfl_xor_sync(0xffffffffu, s,  o);
            s2 += __shfl_xor_sync(0xffffffffu, s2, o);
        }
        if (!l) { ss[0] = s; ss2[0] = s2; }
    }
    __syncthreads();
    float mu  = ss[0] * (1.f / DD);
    float var = ss2[0] * (1.f / DD) - mu * mu;
    float inv = rsqrtf(var + 1e-5f);
    float4 gg = ((const float4*)g)[i];
    float4 bb = ((const float4*)beta)[i];
    __half2 h0, h1;
    h0.x = __float2half_rn((v.x - mu) * inv * gg.x + bb.x);
    h0.y = __float2half_rn((v.y - mu) * inv * gg.y + bb.y);
    h1.x = __float2half_rn((v.z - mu) * inv * gg.z + bb.z);
    h1.y = __float2half_rn((v.w - mu) * inv * gg.w + bb.w);
    size_t base = (size_t)t * DD;
    ((__half2*)(oa + base))[2*i]   = h0;
    ((__half2*)(oa + base))[2*i+1] = h1;
}

// ---------------- minLSTM log-space scan, emits h fp16 ----------------
__global__ void scan_kernel(const float* __restrict__ gates, fp16* __restrict__ ha) {
    int id = blockIdx.x * blockDim.x + threadIdx.x;
    if (id >= BB * EE) return;
    int b = id / EE, e = id % EE;
    const float* lf  = gates + (size_t)b * SS * EE + e;
    const float* lgi = lf + (size_t)TT * EE;
    const float* lth = lf + (size_t)2 * TT * EE;
    fp16* ph = ha + (size_t)b * SS * EE + e;
    float A = 0.f;
    float m = -0.6931471805599453f;   // log(0.5) - 0
    float r = 1.f;
    #pragma unroll 4
    for (int s = 0; s < SS; s++) {
        size_t off = (size_t)s * EE;
        A += lf[off];
        float t = lgi[off] + lth[off] - A;
        if (t <= m) {
            r += expf(t - m);
        } else {
            r = r * expf(m - t) + 1.f;
            m = t;
        }
        ph[off] = __float2half_rn(expf(A + m) * r);
    }
}

// ---------------- launch ----------------
extern "C" void kernel_launch(void* const* d_in, const int* in_sizes, int n_in,
                              void* d_out, int out_size) {
    const float* x      = (const float*)d_in[0];
    const float* cdw_w  = (const float*)d_in[1];
    const float* cdw_b  = (const float*)d_in[2];
    const float* cpw_w  = (const float*)d_in[3];
    const float* cpw_b  = (const float*)d_in[4];
    const float* ln1_g  = (const float*)d_in[5];
    const float* ln1_b  = (const float*)d_in[6];
    const float* w_f    = (const float*)d_in[7];
    const float* w_i    = (const float*)d_in[8];
    const float* w_h    = (const float*)d_in[9];
    const float* w_down = (const float*)d_in[10];
    const float* ln2_g  = (const float*)d_in[11];
    const float* ln2_b  = (const float*)d_in[12];
    const float* mlp_w1 = (const float*)d_in[13];
    const float* mlp_b1 = (const float*)d_in[14];
    const float* mlp_w2 = (const float*)d_in[15];
    const float* mlp_b2 = (const float*)d_in[16];
    float* out = (float*)d_out;

    fp16 *dwa, *x1a, *ha, *x2a, *ma;
    fp16 *pwh, *pwl, *wgh, *wgl, *wdh, *wdl, *m1h, *m1l, *m2h, *m2l;
    float *t1, *gates;
    cudaGetSymbolAddress((void**)&dwa, g_dwa);
    cudaGetSymbolAddress((void**)&t1,  g_t1);
    cudaGetSymbolAddress((void**)&x1a, g_x1a);
    cudaGetSymbolAddress((void**)&gates, g_gates);
    cudaGetSymbolAddress((void**)&ha,  g_ha);
    cudaGetSymbolAddress((void**)&x2a, g_x2a);
    cudaGetSymbolAddress((void**)&ma,  g_ma);
    cudaGetSymbolAddress((void**)&pwh, g_pwh); cudaGetSymbolAddress((void**)&pwl, g_pwl);
    cudaGetSymbolAddress((void**)&wgh, g_wgh); cudaGetSymbolAddress((void**)&wgl, g_wgl);
    cudaGetSymbolAddress((void**)&wdh, g_wdh); cudaGetSymbolAddress((void**)&wdl, g_wdl);
    cudaGetSymbolAddress((void**)&m1h, g_m1h); cudaGetSymbolAddress((void**)&m1l, g_m1l);
    cudaGetSymbolAddress((void**)&m2h, g_m2h); cudaGetSymbolAddress((void**)&m2l, g_m2l);

    cudaFuncSetAttribute(hm_gemm<0,true,false>, cudaFuncAttributeMaxDynamicSharedMemorySize, GEMM_SMEM);
    cudaFuncSetAttribute(hm_gemm<4,true,false>, cudaFuncAttributeMaxDynamicSharedMemorySize, GEMM_SMEM);
    cudaFuncSetAttribute(hm_gemm<3,false,true>, cudaFuncAttributeMaxDynamicSharedMemorySize, GEMM_SMEM);

    // weight splits (w_f/w_i/w_h concatenated into one [3E, D] buffer)
    split_kernel<<<(DD*DD/4 + 255)/256, 256>>>(cpw_w,  pwh, pwl, DD*DD/4);
    split_kernel<<<(EE*DD/4 + 255)/256, 256>>>(w_f, wgh,                   wgl,                   EE*DD/4);
    split_kernel<<<(EE*DD/4 + 255)/256, 256>>>(w_i, wgh + (size_t)EE*DD,   wgl + (size_t)EE*DD,   EE*DD/4);
    split_kernel<<<(EE*DD/4 + 255)/256, 256>>>(w_h, wgh + (size_t)2*EE*DD, wgl + (size_t)2*EE*DD, EE*DD/4);
    split_kernel<<<(DD*EE/4 + 255)/256, 256>>>(w_down, wdh, wdl, DD*EE/4);
    split_kernel<<<(HH*DD/4 + 255)/256, 256>>>(mlp_w1, m1h, m1l, HH*DD/4);
    split_kernel<<<(DD*HH/4 + 255)/256, 256>>>(mlp_w2, m2h, m2l, DD*HH/4);

    // 1) depthwise causal conv -> dwa (fp16)
    dwconv_kernel<<<(TT*DD)/256, 256>>>(x, cdw_w, cdw_b, dwa);

    // 2) pointwise conv + bias + residual(x) -> t1 (fp32)
    hm_gemm<0,true,false><<<dim3(DD/128, TT/128), 256, GEMM_SMEM>>>(
        dwa, pwh, pwl, cpw_b, x, t1, nullptr, TT, DD, DD);

    // 3) LN1 -> x1a (fp16)
    ln_kernel<<<TT, 256>>>(t1, ln1_g, ln1_b, x1a);

    // 4) fused gate GEMM (f|i|h), per-region activation -> gates planes
    hm_gemm<4,true,false><<<dim3(3*EE/128, TT/128), 256, GEMM_SMEM>>>(
        x1a, wgh, wgl, nullptr, nullptr, gates, nullptr, TT, 3*EE, DD);

    // 5) scan -> h (fp16)
    scan_kernel<<<(BB*EE + 127)/128, 128>>>(gates, ha);

    // 6) down GEMM + residual(x) -> t1
    hm_gemm<0,true,false><<<dim3(DD/128, TT/128), 256, GEMM_SMEM>>>(
        ha, wdh, wdl, nullptr, x, t1, nullptr, TT, DD, EE);

    // 7) LN2 -> x2a (fp16)
    ln_kernel<<<TT, 256>>>(t1, ln2_g, ln2_b, x2a);

    // 8) MLP up + bias + GELU -> ma (fp16)
    hm_gemm<3,false,true><<<dim3(HH/128, TT/128), 256, GEMM_SMEM>>>(
        x2a, m1h, m1l, mlp_b1, nullptr, nullptr, ma, TT, HH, DD);

    // 9) MLP down + bias -> out (fp32)
    hm_gemm<0,true,false><<<dim3(DD/128, TT/128), 256, GEMM_SMEM>>>(
        ma, m2h, m2l, mlp_b2, nullptr, out, nullptr, TT, DD, HH);
}